// round 5
// baseline (speedup 1.0000x reference)
#include <cuda_runtime.h>

// Piecewise-linear log-sigmoid approximation.
// inputs (metadata order): vals[64*2048*2048] f32, x[65] f32, y[65] f32
// output: f32, same shape as vals.
//
// Reference semantics:
//   v <  x[0]  -> v (identity)
//   v >= x[64] -> 0
//   else idx = clamp(searchsorted(x, v, right)-1, 0, 63)
//        out = y[idx] + (v - x[idx]) * (y[idx+1]-y[idx])/(x[idx+1]-x[idx])
//
// x is a uniform linspace, so the bucket index is pure arithmetic:
//   idx = min((int)((v - x0) * 64/(x64-x0)), 63)
// Boundary mis-buckets are harmless by continuity of the piecewise-linear fn.

#define NBP  65
#define NSEG 64

__global__ void logsig_kernel(const float* __restrict__ vals,
                              const float* __restrict__ xs,
                              const float* __restrict__ ys,
                              float* __restrict__ out,
                              long long n4)
{
    // Per-segment affine coefficients: out = c.x + c.y * v
    __shared__ float2 coef[NSEG];
    __shared__ float s_x0, s_xlast, s_invh;

    const int t = threadIdx.x;
    if (t < NSEG) {
        float x0 = xs[t];
        float x1 = xs[t + 1];
        float y0 = ys[t];
        float y1 = ys[t + 1];
        float slope = (y1 - y0) / (x1 - x0);
        coef[t] = make_float2(fmaf(-x0, slope, y0), slope);
    }
    if (t == 0) {
        float a = xs[0];
        float b = xs[NBP - 1];
        s_x0    = a;
        s_xlast = b;
        s_invh  = (float)NSEG / (b - a);
    }
    __syncthreads();

    const float x0    = s_x0;
    const float xlast = s_xlast;
    const float invh  = s_invh;

    long long i = (long long)blockIdx.x * blockDim.x + t;
    if (i >= n4) return;

    float4 v = reinterpret_cast<const float4*>(vals)[i];
    float4 o;

    float vv[4] = {v.x, v.y, v.z, v.w};
    float oo[4];
    #pragma unroll
    for (int k = 0; k < 4; k++) {
        float val = vv[k];
        float r;
        if (val < x0) {
            r = val;                 // identity below first breakpoint
        } else if (val >= xlast) {
            r = 0.0f;                // never assigned in torch loop -> zero
        } else {
            int idx = (int)((val - x0) * invh);
            idx = min(idx, NSEG - 1);
            float2 c = coef[idx];
            r = fmaf(c.y, val, c.x);
        }
        oo[k] = r;
    }
    o.x = oo[0]; o.y = oo[1]; o.z = oo[2]; o.w = oo[3];
    reinterpret_cast<float4*>(out)[i] = o;
}

extern "C" void kernel_launch(void* const* d_in, const int* in_sizes, int n_in,
                              void* d_out, int out_size)
{
    const float* vals = (const float*)d_in[0];
    const float* xs   = (const float*)d_in[1];
    const float* ys   = (const float*)d_in[2];
    float* out        = (float*)d_out;

    long long n  = (long long)out_size;   // 268,435,456 (divisible by 4)
    long long n4 = n / 4;

    const int threads = 256;
    long long blocks = (n4 + threads - 1) / threads;

    logsig_kernel<<<(unsigned)blocks, threads>>>(vals, xs, ys, out, n4);
}

// round 6
// speedup vs baseline: 1.0014x; 1.0014x over previous
#include <cuda_runtime.h>

// Piecewise-linear log-sigmoid approximation.
// inputs (metadata order): vals[64*2048*2048] f32, x[65] f32, y[65] f32
// output: f32, same shape as vals.
//
// Reference semantics:
//   v <  x[0]  -> v (identity)
//   v >= x[64] -> 0
//   else idx = clamp(searchsorted(x, v, right)-1, 0, 63)
//        out = y[idx] + (v - x[idx]) * (y[idx+1]-y[idx])/(x[idx+1]-x[idx])
//
// x is a uniform linspace, so the bucket index is pure arithmetic:
//   idx = min((int)((v - x0) * 64/(x64-x0)), 63)
// Boundary mis-buckets are harmless by continuity of the piecewise-linear fn.

#define NBP  65
#define NSEG 64

__global__ void logsig_kernel(const float* __restrict__ vals,
                              const float* __restrict__ xs,
                              const float* __restrict__ ys,
                              float* __restrict__ out,
                              long long n4)
{
    // Per-segment affine coefficients: out = c.x + c.y * v
    __shared__ float2 coef[NSEG];
    __shared__ float s_x0, s_xlast, s_invh;

    const int t = threadIdx.x;
    if (t < NSEG) {
        float x0 = xs[t];
        float x1 = xs[t + 1];
        float y0 = ys[t];
        float y1 = ys[t + 1];
        float slope = (y1 - y0) / (x1 - x0);
        coef[t] = make_float2(fmaf(-x0, slope, y0), slope);
    }
    if (t == 0) {
        float a = xs[0];
        float b = xs[NBP - 1];
        s_x0    = a;
        s_xlast = b;
        s_invh  = (float)NSEG / (b - a);
    }
    __syncthreads();

    const float x0    = s_x0;
    const float xlast = s_xlast;
    const float invh  = s_invh;

    long long i = (long long)blockIdx.x * blockDim.x + t;
    if (i >= n4) return;

    float4 v = reinterpret_cast<const float4*>(vals)[i];
    float4 o;

    float vv[4] = {v.x, v.y, v.z, v.w};
    float oo[4];
    #pragma unroll
    for (int k = 0; k < 4; k++) {
        float val = vv[k];
        float r;
        if (val < x0) {
            r = val;                 // identity below first breakpoint
        } else if (val >= xlast) {
            r = 0.0f;                // never assigned in torch loop -> zero
        } else {
            int idx = (int)((val - x0) * invh);
            idx = min(idx, NSEG - 1);
            float2 c = coef[idx];
            r = fmaf(c.y, val, c.x);
        }
        oo[k] = r;
    }
    o.x = oo[0]; o.y = oo[1]; o.z = oo[2]; o.w = oo[3];
    reinterpret_cast<float4*>(out)[i] = o;
}

extern "C" void kernel_launch(void* const* d_in, const int* in_sizes, int n_in,
                              void* d_out, int out_size)
{
    const float* vals = (const float*)d_in[0];
    const float* xs   = (const float*)d_in[1];
    const float* ys   = (const float*)d_in[2];
    float* out        = (float*)d_out;

    long long n  = (long long)out_size;   // 268,435,456 (divisible by 4)
    long long n4 = n / 4;

    const int threads = 256;
    long long blocks = (n4 + threads - 1) / threads;

    logsig_kernel<<<(unsigned)blocks, threads>>>(vals, xs, ys, out, n4);
}

// round 7
// speedup vs baseline: 1.0023x; 1.0009x over previous
#include <cuda_runtime.h>

// Piecewise-linear log-sigmoid approximation.
// inputs (metadata order): vals[64*2048*2048] f32, x[65] f32, y[65] f32
// output: f32, same shape as vals.
//
// Reference semantics:
//   v <  x[0]  -> v (identity)
//   v >= x[64] -> 0
//   else idx = clamp(searchsorted(x, v, right)-1, 0, 63)
//        out = y[idx] + (v - x[idx]) * (y[idx+1]-y[idx])/(x[idx+1]-x[idx])
//
// x is a uniform linspace, so the bucket index is pure arithmetic:
//   idx = min((int)((v - x0) * 64/(x64-x0)), 63)
// Boundary mis-buckets are harmless by continuity of the piecewise-linear fn.

#define NBP  65
#define NSEG 64

__global__ void logsig_kernel(const float* __restrict__ vals,
                              const float* __restrict__ xs,
                              const float* __restrict__ ys,
                              float* __restrict__ out,
                              long long n4)
{
    // Per-segment affine coefficients: out = c.x + c.y * v
    __shared__ float2 coef[NSEG];
    __shared__ float s_x0, s_xlast, s_invh;

    const int t = threadIdx.x;
    if (t < NSEG) {
        float x0 = xs[t];
        float x1 = xs[t + 1];
        float y0 = ys[t];
        float y1 = ys[t + 1];
        float slope = (y1 - y0) / (x1 - x0);
        coef[t] = make_float2(fmaf(-x0, slope, y0), slope);
    }
    if (t == 0) {
        float a = xs[0];
        float b = xs[NBP - 1];
        s_x0    = a;
        s_xlast = b;
        s_invh  = (float)NSEG / (b - a);
    }
    __syncthreads();

    const float x0    = s_x0;
    const float xlast = s_xlast;
    const float invh  = s_invh;

    long long i = (long long)blockIdx.x * blockDim.x + t;
    if (i >= n4) return;

    float4 v = reinterpret_cast<const float4*>(vals)[i];
    float4 o;

    float vv[4] = {v.x, v.y, v.z, v.w};
    float oo[4];
    #pragma unroll
    for (int k = 0; k < 4; k++) {
        float val = vv[k];
        float r;
        if (val < x0) {
            r = val;                 // identity below first breakpoint
        } else if (val >= xlast) {
            r = 0.0f;                // never assigned in torch loop -> zero
        } else {
            int idx = (int)((val - x0) * invh);
            idx = min(idx, NSEG - 1);
            float2 c = coef[idx];
            r = fmaf(c.y, val, c.x);
        }
        oo[k] = r;
    }
    o.x = oo[0]; o.y = oo[1]; o.z = oo[2]; o.w = oo[3];
    reinterpret_cast<float4*>(out)[i] = o;
}

extern "C" void kernel_launch(void* const* d_in, const int* in_sizes, int n_in,
                              void* d_out, int out_size)
{
    const float* vals = (const float*)d_in[0];
    const float* xs   = (const float*)d_in[1];
    const float* ys   = (const float*)d_in[2];
    float* out        = (float*)d_out;

    long long n  = (long long)out_size;   // 268,435,456 (divisible by 4)
    long long n4 = n / 4;

    const int threads = 256;
    long long blocks = (n4 + threads - 1) / threads;

    logsig_kernel<<<(unsigned)blocks, threads>>>(vals, xs, ys, out, n4);
}

// round 8
// speedup vs baseline: 1.0025x; 1.0002x over previous
#include <cuda_runtime.h>

// Piecewise-linear log-sigmoid approximation.
// inputs (metadata order): vals[64*2048*2048] f32, x[65] f32, y[65] f32
// output: f32, same shape as vals.
//
// Reference semantics:
//   v <  x[0]  -> v (identity)
//   v >= x[64] -> 0
//   else idx = clamp(searchsorted(x, v, right)-1, 0, 63)
//        out = y[idx] + (v - x[idx]) * (y[idx+1]-y[idx])/(x[idx+1]-x[idx])
//
// x is a uniform linspace, so the bucket index is pure arithmetic:
//   idx = min((int)((v - x0) * 64/(x64-x0)), 63)
// Boundary mis-buckets are harmless by continuity of the piecewise-linear fn.

#define NBP  65
#define NSEG 64

__global__ void logsig_kernel(const float* __restrict__ vals,
                              const float* __restrict__ xs,
                              const float* __restrict__ ys,
                              float* __restrict__ out,
                              long long n4)
{
    // Per-segment affine coefficients: out = c.x + c.y * v
    __shared__ float2 coef[NSEG];
    __shared__ float s_x0, s_xlast, s_invh;

    const int t = threadIdx.x;
    if (t < NSEG) {
        float x0 = xs[t];
        float x1 = xs[t + 1];
        float y0 = ys[t];
        float y1 = ys[t + 1];
        float slope = (y1 - y0) / (x1 - x0);
        coef[t] = make_float2(fmaf(-x0, slope, y0), slope);
    }
    if (t == 0) {
        float a = xs[0];
        float b = xs[NBP - 1];
        s_x0    = a;
        s_xlast = b;
        s_invh  = (float)NSEG / (b - a);
    }
    __syncthreads();

    const float x0    = s_x0;
    const float xlast = s_xlast;
    const float invh  = s_invh;

    long long i = (long long)blockIdx.x * blockDim.x + t;
    if (i >= n4) return;

    float4 v = reinterpret_cast<const float4*>(vals)[i];
    float4 o;

    float vv[4] = {v.x, v.y, v.z, v.w};
    float oo[4];
    #pragma unroll
    for (int k = 0; k < 4; k++) {
        float val = vv[k];
        float r;
        if (val < x0) {
            r = val;                 // identity below first breakpoint
        } else if (val >= xlast) {
            r = 0.0f;                // never assigned in torch loop -> zero
        } else {
            int idx = (int)((val - x0) * invh);
            idx = min(idx, NSEG - 1);
            float2 c = coef[idx];
            r = fmaf(c.y, val, c.x);
        }
        oo[k] = r;
    }
    o.x = oo[0]; o.y = oo[1]; o.z = oo[2]; o.w = oo[3];
    reinterpret_cast<float4*>(out)[i] = o;
}

extern "C" void kernel_launch(void* const* d_in, const int* in_sizes, int n_in,
                              void* d_out, int out_size)
{
    const float* vals = (const float*)d_in[0];
    const float* xs   = (const float*)d_in[1];
    const float* ys   = (const float*)d_in[2];
    float* out        = (float*)d_out;

    long long n  = (long long)out_size;   // 268,435,456 (divisible by 4)
    long long n4 = n / 4;

    const int threads = 256;
    long long blocks = (n4 + threads - 1) / threads;

    logsig_kernel<<<(unsigned)blocks, threads>>>(vals, xs, ys, out, n4);
}